// round 12
// baseline (speedup 1.0000x reference)
#include <cuda_runtime.h>
#include <cstdint>

constexpr int NTR = 4096;
constexpr int NTE = 2048;
constexpr int DIM = 16;
constexpr int NIT = 13;          // Chebyshev iterations for alpha

// ---- device scratch ----
__device__ float g_K   [(size_t)NTR * NTR];   // fp32 K (matvec + rowsum)
__device__ float g_Ktf [(size_t)NTR * NTR];   // tf32-rounded K (GEMM A)
__device__ float g_Ks  [(size_t)NTR * NTE];   // fp32 Kstar (dots)
__device__ float g_Kstf[(size_t)NTR * NTE];   // rounded Kstar (GEMM-1 B operand)
__device__ float g_Z1  [(size_t)NTR * NTE];
__device__ float g_Z2  [(size_t)NTR * NTE];
__device__ float g_xs[NTR * DIM];
__device__ float g_ts[NTE * DIM];
__device__ float g_sqx[NTR];
__device__ float g_sqt[NTE];
__device__ float g_rowsum[NTR];
__device__ float g_xv[NTR];                   // cheb solution (alpha)
__device__ float g_rv[NTR];                   // cheb residual
__device__ float g_da[NTR], g_db[NTR];        // cheb direction (double buffer)
__device__ float g_spec[4];                   // theta, delta, 1/theta
__device__ float g_poly[5];                   // s*a0..s*a4 (degree 4)
__device__ float g_c1[NIT + 2], g_c2[NIT + 2];
__device__ float g_partM[16 * NTE];
__device__ float g_partD[16 * 5 * NTE];
__device__ float g_params[2];                 // sigmaf2, sigman2
__device__ float g_scale[DIM];
__device__ unsigned g_barc;                   // global barrier counter
__device__ unsigned g_barg;                   // global barrier generation

// ---- helpers ----
__device__ __forceinline__ float tf32r(float x) {
    uint32_t u; asm("cvt.rna.tf32.f32 %0, %1;" : "=r"(u) : "f"(x));
    return __uint_as_float(u);
}
__device__ __forceinline__ void mma_tf32(float* d, const uint32_t* a, const uint32_t* b) {
    asm volatile(
        "mma.sync.aligned.m16n8k8.row.col.f32.tf32.tf32.f32 "
        "{%0,%1,%2,%3},{%4,%5,%6,%7},{%8,%9},{%0,%1,%2,%3};"
        : "+f"(d[0]), "+f"(d[1]), "+f"(d[2]), "+f"(d[3])
        : "r"(a[0]), "r"(a[1]), "r"(a[2]), "r"(a[3]), "r"(b[0]), "r"(b[1]));
}
__device__ __forceinline__ void cpa16(uint32_t dst, const void* src) {
    asm volatile("cp.async.cg.shared.global [%0], [%1], 16;\n" :: "r"(dst), "l"(src));
}

// ---- grid-wide spin barrier (all blocks co-resident by construction) ----
__device__ __forceinline__ void gbar() {
    __syncthreads();
    if (threadIdx.x == 0) {
        __threadfence();
        unsigned gen = *(volatile unsigned*)&g_barg;
        unsigned a = atomicAdd(&g_barc, 1u);
        if (a == gridDim.x - 1) {
            g_barc = 0;
            __threadfence();
            *(volatile unsigned*)&g_barg = gen + 1;
        } else {
            while (*(volatile unsigned*)&g_barg == gen) __nanosleep(40);
        }
        __threadfence();
    }
    __syncthreads();
}

// ---- prep / builders ----
__global__ void k_prep(const float* lsf2, const float* ll2, const float* lsn2) {
    int t = threadIdx.x;
    if (t == 0) { g_params[0] = expf(lsf2[0]); g_params[1] = expf(lsn2[0]); }
    if (t < DIM) g_scale[t] = sqrtf(0.5f * expf(-ll2[t]));
}

__global__ void k_scale(const float* __restrict__ in, float* __restrict__ out,
                        float* __restrict__ sq, int n) {
    int i = blockIdx.x * blockDim.x + threadIdx.x;
    if (i >= n) return;
    float s = 0.f;
#pragma unroll
    for (int d = 0; d < DIM; d++) {
        float v = in[i * DIM + d] * g_scale[d];
        out[i * DIM + d] = v;
        s += v * v;
    }
    sq[i] = s;
}

__global__ void k_build_knn() {
    __shared__ float A[32][DIM];
    __shared__ float B[32][DIM + 1];
    int bi = blockIdx.y * 32, bj = blockIdx.x * 32;
    int t = threadIdx.x;
    for (int idx = t; idx < 32 * DIM; idx += 256) {
        int r = idx / DIM, d = idx % DIM;
        A[r][d] = g_xs[(bi + r) * DIM + d];
        B[r][d] = g_xs[(bj + r) * DIM + d];
    }
    __syncthreads();
    float sf2 = g_params[0], sn2 = g_params[1];
    int tx = t & 31, ty = t >> 5;
    int j = bj + tx;
    float sqj = g_sqx[j];
#pragma unroll
    for (int q = 0; q < 4; q++) {
        int li = ty * 4 + q, i = bi + li;
        float dot = 0.f;
#pragma unroll
        for (int d = 0; d < DIM; d++) dot += A[li][d] * B[tx][d];
        float d2 = fmaxf(g_sqx[i] + sqj - 2.f * dot, 0.f);
        float v = sf2 * expf(-d2);
        if (i == j) v += sn2;
        g_K  [(size_t)i * NTR + j] = v;
        g_Ktf[(size_t)i * NTR + j] = tf32r(v);
    }
}

__global__ void k_build_ks() {
    __shared__ float A[32][DIM];
    __shared__ float B[32][DIM + 1];
    int bi = blockIdx.y * 32, bj = blockIdx.x * 32;
    int t = threadIdx.x;
    for (int idx = t; idx < 32 * DIM; idx += 256) {
        int r = idx / DIM, d = idx % DIM;
        A[r][d] = g_xs[(bi + r) * DIM + d];
        B[r][d] = g_ts[(bj + r) * DIM + d];
    }
    __syncthreads();
    float sf2 = g_params[0];
    int tx = t & 31, ty = t >> 5;
    int j = bj + tx;
    float sqj = g_sqt[j];
#pragma unroll
    for (int q = 0; q < 4; q++) {
        int li = ty * 4 + q, i = bi + li;
        float dot = 0.f;
#pragma unroll
        for (int d = 0; d < DIM; d++) dot += A[li][d] * B[tx][d];
        float d2 = fmaxf(g_sqx[i] + sqj - 2.f * dot, 0.f);
        float v = sf2 * expf(-d2);
        g_Ks  [(size_t)i * NTE + j] = v;
        g_Kstf[(size_t)i * NTE + j] = tf32r(v);
    }
}

// ---- row sums (deterministic, warp per row) ----
__global__ void k_rowsum() {
    int t = threadIdx.x, lane = t & 31, w = t >> 5;
    int row = blockIdx.x * 8 + w;
    const float* Kr = g_K + (size_t)row * NTR;
    float s = 0.f;
    for (int j = lane; j < NTR; j += 32) s += Kr[j];
#pragma unroll
    for (int o = 16; o; o >>= 1) s += __shfl_down_sync(0xffffffffu, s, o);
    if (lane == 0) g_rowsum[row] = s;
}

// ---- spectrum bounds -> deg-4 poly coeffs + cheb schedule + barrier reset ----
__global__ void k_spec() {
    __shared__ float sm[1024];
    int t = threadIdx.x;
    float m = 0.f;
    for (int i = t; i < NTR; i += 1024) m = fmaxf(m, g_rowsum[i]);
    sm[t] = m;
    __syncthreads();
    for (int o = 512; o; o >>= 1) {
        if (t < o) sm[t] = fmaxf(sm[t], sm[t + o]);
        __syncthreads();
    }
    if (t == 0) {
        g_barc = 0u;                 // deterministic barrier state per replay
        g_barg = 0u;
        float b = sm[0];
        float sf2 = g_params[0], sn2 = g_params[1];
        float diag = sf2 + sn2;
        float a = fmaxf(sn2, 2.f * diag - b);
        if (!(a < b)) a = 0.5f * b;
        float theta = 0.5f * (a + b);
        float delta = fmaxf(0.5f * (b - a), 1e-6f * theta);
        float gamma = theta / delta;
        float rho   = 1.f / (gamma + sqrtf(gamma * gamma - 1.f));
        float r2 = rho * rho, r3 = r2 * rho, r4 = r2 * r2;
        float s = 2.f * rho / (delta * (1.f - r2));
        g_poly[0] = s * (1.f - 2.f * r2 + 2.f * r4);
        g_poly[1] = s * (-2.f * rho + 6.f * r3);
        g_poly[2] = s * (4.f * r2 - 16.f * r4);
        g_poly[3] = s * (-8.f * r3);
        g_poly[4] = s * (16.f * r4);
        g_spec[0] = theta; g_spec[1] = delta; g_spec[2] = 1.f / theta;
        float sig1 = gamma, rc = 1.f / sig1;
        for (int k = 1; k <= NIT + 1; k++) {
            float rn = 1.f / (2.f * sig1 - rc);
            g_c1[k] = rn * rc;
            g_c2[k] = 2.f * rn / delta;
            rc = rn;
        }
    }
}

// ---- big tensor GEMM: Z = tf32r((A*B - theta*B) / delta), NN, K-dim=4096 ----
// 128 threads, 128x128 tile, warp grid 2x2, BK=32, 3-stage cp.async, 2 blk/SM
__global__ void __launch_bounds__(128, 2) k_gemmU(
    const float* __restrict__ A,     // g_Ktf, lda = NTR
    const float* __restrict__ B,     // rounded input, ldb = NTE
    float* __restrict__ Z)           // ldc = NTE
{
    extern __shared__ float sm[];
    constexpr int ASTG = 128 * 36;   // [m][k] pad 36 (BK=32 + 4)
    constexpr int BSTG = 32 * 136;   // [k][n] pad 136
    constexpr int NS   = NTR / 32;   // 128 slices
    const int row0 = blockIdx.y * 128, col0 = blockIdx.x * 128;
    const int t = threadIdx.x;
    const int lane = t & 31, wid = t >> 5;
    const int wm = wid & 1, wn = wid >> 1;     // 2 x 2 warp grid
    const int g = lane >> 2, tig = lane & 3;
    const uint32_t smbase = (uint32_t)__cvta_generic_to_shared(sm);
    const int brow = t >> 2, bc4 = (t & 3) * 32;   // B staging: row, col-base
    const float theta = g_spec[0];
    const float idel  = 1.f / g_spec[1];

    auto issue = [&](int s, int stg) {
        const int k0 = s * 32;
        const float* srcA = A + (size_t)(row0 + t) * NTR + k0;
        uint32_t dstA = smbase + (uint32_t)(stg * ASTG + t * 36) * 4u;
#pragma unroll
        for (int j = 0; j < 8; j++) cpa16(dstA + j * 16, srcA + j * 4);
        const float* srcB = B + (size_t)(k0 + brow) * NTE + col0 + bc4;
        uint32_t dstB = smbase + (uint32_t)(3 * ASTG + stg * BSTG + brow * 136 + bc4) * 4u;
#pragma unroll
        for (int j = 0; j < 8; j++) cpa16(dstB + j * 16, srcB + j * 4);
        asm volatile("cp.async.commit_group;\n");
    };

    float acc[4][8][4];
#pragma unroll
    for (int i = 0; i < 4; i++)
#pragma unroll
        for (int j = 0; j < 8; j++)
#pragma unroll
            for (int q = 0; q < 4; q++) acc[i][j][q] = 0.f;

    issue(0, 0); issue(1, 1);
    int cur = 0, nxt = 2;
    for (int s = 0; s < NS; s++) {
        if (s < NS - 1) asm volatile("cp.async.wait_group 1;\n");
        else            asm volatile("cp.async.wait_group 0;\n");
        __syncthreads();
        if (s + 2 < NS) issue(s + 2, nxt);
        const float* Asb = sm + cur * ASTG;
        const float* Bsb = sm + 3 * ASTG + cur * BSTG;
#pragma unroll
        for (int kf = 0; kf < 4; kf++) {
            const int kb = kf * 8;
            uint32_t a[4][4], b[8][2];
#pragma unroll
            for (int mt = 0; mt < 4; mt++) {
                int rb = wm * 64 + mt * 16 + g;
                a[mt][0] = __float_as_uint(Asb[rb * 36 + kb + tig]);
                a[mt][1] = __float_as_uint(Asb[(rb + 8) * 36 + kb + tig]);
                a[mt][2] = __float_as_uint(Asb[rb * 36 + kb + tig + 4]);
                a[mt][3] = __float_as_uint(Asb[(rb + 8) * 36 + kb + tig + 4]);
            }
#pragma unroll
            for (int nt = 0; nt < 8; nt++) {
                int cb = wn * 64 + nt * 8 + g;
                b[nt][0] = __float_as_uint(Bsb[(kb + tig) * 136 + cb]);
                b[nt][1] = __float_as_uint(Bsb[(kb + tig + 4) * 136 + cb]);
            }
#pragma unroll
            for (int mt = 0; mt < 4; mt++)
#pragma unroll
                for (int nt = 0; nt < 8; nt++)
                    mma_tf32(acc[mt][nt], a[mt], b[nt]);
        }
        __syncthreads();
        cur = (cur == 2) ? 0 : cur + 1;
        nxt = (nxt == 2) ? 0 : nxt + 1;
    }

    // epilogue: Z = tf32r((acc - theta*B)/delta)
#pragma unroll
    for (int mt = 0; mt < 4; mt++) {
        int r0 = row0 + wm * 64 + mt * 16 + g;
#pragma unroll
        for (int nt = 0; nt < 8; nt++) {
            int c = col0 + wn * 64 + nt * 8 + tig * 2;
            float2 x0 = *(const float2*)(B + (size_t)r0 * NTE + c);
            float2 x1 = *(const float2*)(B + (size_t)(r0 + 8) * NTE + c);
            *(float2*)(Z + (size_t)r0 * NTE + c) = make_float2(
                tf32r((acc[mt][nt][0] - theta * x0.x) * idel),
                tf32r((acc[mt][nt][1] - theta * x0.y) * idel));
            *(float2*)(Z + (size_t)(r0 + 8) * NTE + c) = make_float2(
                tf32r((acc[mt][nt][2] - theta * x1.x) * idel),
                tf32r((acc[mt][nt][3] - theta * x1.y) * idel));
        }
    }
}

// ---- fused Chebyshev semi-iteration: alpha = K^{-1} y, ONE launch ----
// 128 blocks x 1024 threads (warp-per-row): 131K threads for DRAM MLP.
__global__ void k_cheb(const float* __restrict__ y) {
    const int t = threadIdx.x, lane = t & 31, w = t >> 5;   // 32 warps
    const int row = blockIdx.x * 32 + w;
    if (t < 32) {
        int r = blockIdx.x * 32 + t;
        float yv = y[r];
        g_xv[r] = 0.f;
        g_rv[r] = yv;
        g_da[r] = yv * g_spec[2];
    }
    gbar();
    float* din = g_da;
    float* dout = g_db;
    const float4* Kr = (const float4*)(g_K + (size_t)row * NTR);
    for (int k = 1; k <= NIT; k++) {
        float c1 = g_c1[k], c2 = g_c2[k];
        const float4* dv4 = (const float4*)din;
        float s = 0.f;
#pragma unroll 4
        for (int j = lane; j < NTR / 4; j += 32) {
            float4 kv = Kr[j], dd = dv4[j];
            s += kv.x * dd.x + kv.y * dd.y + kv.z * dd.z + kv.w * dd.w;
        }
#pragma unroll
        for (int o = 16; o; o >>= 1) s += __shfl_down_sync(0xffffffffu, s, o);
        if (lane == 0) {
            float dv = din[row];
            g_xv[row] += dv;
            float rv = g_rv[row] - s;
            g_rv[row] = rv;
            dout[row] = c1 * dv + c2 * rv;
        }
        gbar();
        float* tmp = din; din = dout; dout = tmp;
    }
    if (t < 32) {
        int r = blockIdx.x * 32 + t;
        g_xv[r] += din[r];
    }
}

// ---- fused dots: mean partial + 5 moment partials (deg-4) ----
__global__ void k_dots() {            // grid (NTE/256, 16), 256 threads
    __shared__ float sa[256];
    int t = threadIdx.x;
    int n0 = blockIdx.y * 256;
    sa[t] = g_xv[n0 + t];
    __syncthreads();
    int m = blockIdx.x * 256 + t;
    float dm = 0, d00 = 0, d01 = 0, d11 = 0, d12 = 0, d22 = 0;
    for (int q = 0; q < 256; q++) {
        size_t off = (size_t)(n0 + q) * NTE + m;
        float kf = g_Ks[off];
        float z1 = g_Z1[off], z2 = g_Z2[off];
        dm  += kf * sa[q];
        d00 += kf * kf; d01 += kf * z1; d11 += z1 * z1;
        d12 += z1 * z2; d22 += z2 * z2;
    }
    g_partM[blockIdx.y * NTE + m] = dm;
    float* pd = g_partD + (size_t)blockIdx.y * 5 * NTE + m;
    pd[0 * NTE] = d00; pd[1 * NTE] = d01; pd[2 * NTE] = d11;
    pd[3 * NTE] = d12; pd[4 * NTE] = d22;
}

__global__ void k_finalize(float* out) {
    int m = blockIdx.x * 256 + threadIdx.x;
    if (m >= NTE) return;
    float sm = 0.f, D[5] = {0, 0, 0, 0, 0};
    for (int p = 0; p < 16; p++) {
        sm += g_partM[p * NTE + m];
        const float* pd = g_partD + (size_t)p * 5 * NTE + m;
#pragma unroll
        for (int j = 0; j < 5; j++) D[j] += pd[j * NTE];
    }
    float q = 0.f;
#pragma unroll
    for (int j = 0; j < 5; j++) q += g_poly[j] * D[j];
    out[m] = sm;
    out[NTE + m] = g_params[0] + g_params[1] - q;
}

// ---- launch ----
extern "C" void kernel_launch(void* const* d_in, const int* in_sizes, int n_in,
                              void* d_out, int out_size)
{
    const float* train_x = (const float*)d_in[0];
    const float* train_y = (const float*)d_in[1];
    const float* test_x  = (const float*)d_in[2];
    const float* lsf2    = (const float*)d_in[3];
    const float* ll2     = (const float*)d_in[4];
    const float* lsn2    = (const float*)d_in[5];
    float* out = (float*)d_out;

    float *pKtf, *pKstf, *pZ1, *pZ2, *pXs, *pTs, *pSqx, *pSqt;
    cudaGetSymbolAddress((void**)&pKtf,  g_Ktf);
    cudaGetSymbolAddress((void**)&pKstf, g_Kstf);
    cudaGetSymbolAddress((void**)&pZ1,   g_Z1);
    cudaGetSymbolAddress((void**)&pZ2,   g_Z2);
    cudaGetSymbolAddress((void**)&pXs,   g_xs);
    cudaGetSymbolAddress((void**)&pTs,   g_ts);
    cudaGetSymbolAddress((void**)&pSqx,  g_sqx);
    cudaGetSymbolAddress((void**)&pSqt,  g_sqt);

    const int smem_gemm = 3 * (128 * 36 + 32 * 136) * sizeof(float);  // 107520
    cudaFuncSetAttribute(k_gemmU, cudaFuncAttributeMaxDynamicSharedMemorySize, smem_gemm);

    k_prep<<<1, 32>>>(lsf2, ll2, lsn2);
    k_scale<<<(NTR + 255) / 256, 256>>>(train_x, pXs, pSqx, NTR);
    k_scale<<<(NTE + 255) / 256, 256>>>(test_x,  pTs, pSqt, NTE);
    k_build_knn<<<dim3(NTR / 32, NTR / 32), 256>>>();
    k_build_ks <<<dim3(NTE / 32, NTR / 32), 256>>>();
    k_rowsum<<<NTR / 8, 256>>>();
    k_spec<<<1, 1024>>>();

    // mean path: one fused launch, 131K threads
    k_cheb<<<128, 1024>>>(train_y);

    // variance path: Z1 = U*Ks, Z2 = U*Z1 (BK=32 GEMM)
    dim3 ggrid(NTE / 128, NTR / 128);
    k_gemmU<<<ggrid, 128, smem_gemm>>>(pKtf, pKstf, pZ1);
    k_gemmU<<<ggrid, 128, smem_gemm>>>(pKtf, pZ1,   pZ2);

    k_dots<<<dim3(NTE / 256, 16), 256>>>();
    k_finalize<<<(NTE + 255) / 256, 256>>>(out);
}

// round 13
// speedup vs baseline: 1.3868x; 1.3868x over previous
#include <cuda_runtime.h>
#include <cstdint>

constexpr int NTR = 4096;
constexpr int NTE = 2048;
constexpr int DIM = 16;
constexpr int NIT = 13;          // Chebyshev iterations for alpha

// ---- device scratch ----
__device__ float g_K   [(size_t)NTR * NTR];   // fp32 K (matvec + rowsum)
__device__ float g_Ktf [(size_t)NTR * NTR];   // tf32-rounded K (GEMM A)
__device__ float g_Ks  [(size_t)NTR * NTE];   // fp32 Kstar (dots)
__device__ float g_Kstf[(size_t)NTR * NTE];   // rounded Kstar (GEMM-1 B operand)
__device__ float g_Z1  [(size_t)NTR * NTE];
__device__ float g_Z2  [(size_t)NTR * NTE];
__device__ float g_xs[NTR * DIM];
__device__ float g_ts[NTE * DIM];
__device__ float g_sqx[NTR];
__device__ float g_sqt[NTE];
__device__ float g_rowsum[NTR];
__device__ float g_xv[NTR];                   // cheb solution (alpha)
__device__ float g_rv[NTR];                   // cheb residual
__device__ float g_da[NTR], g_db[NTR];        // cheb direction (double buffer)
__device__ float g_spec[4];                   // theta, delta, 1/theta
__device__ float g_poly[5];                   // s*a0..s*a4 (degree 4)
__device__ float g_c1[NIT + 2], g_c2[NIT + 2];
__device__ float g_partM[8 * NTE];
__device__ float g_partD[8 * 5 * NTE];
__device__ float g_params[2];                 // sigmaf2, sigman2
__device__ float g_scale[DIM];

// ---- helpers ----
__device__ __forceinline__ float tf32r(float x) {
    uint32_t u; asm("cvt.rna.tf32.f32 %0, %1;" : "=r"(u) : "f"(x));
    return __uint_as_float(u);
}
__device__ __forceinline__ void mma_tf32(float* d, const uint32_t* a, const uint32_t* b) {
    asm volatile(
        "mma.sync.aligned.m16n8k8.row.col.f32.tf32.tf32.f32 "
        "{%0,%1,%2,%3},{%4,%5,%6,%7},{%8,%9},{%0,%1,%2,%3};"
        : "+f"(d[0]), "+f"(d[1]), "+f"(d[2]), "+f"(d[3])
        : "r"(a[0]), "r"(a[1]), "r"(a[2]), "r"(a[3]), "r"(b[0]), "r"(b[1]));
}
__device__ __forceinline__ void cpa16(uint32_t dst, const void* src) {
    asm volatile("cp.async.cg.shared.global [%0], [%1], 16;\n" :: "r"(dst), "l"(src));
}

// ---- prep / builders ----
__global__ void k_prep(const float* lsf2, const float* ll2, const float* lsn2) {
    int t = threadIdx.x;
    if (t == 0) { g_params[0] = expf(lsf2[0]); g_params[1] = expf(lsn2[0]); }
    if (t < DIM) g_scale[t] = sqrtf(0.5f * expf(-ll2[t]));
}

__global__ void k_scale(const float* __restrict__ in, float* __restrict__ out,
                        float* __restrict__ sq, int n) {
    int i = blockIdx.x * blockDim.x + threadIdx.x;
    if (i >= n) return;
    float s = 0.f;
#pragma unroll
    for (int d = 0; d < DIM; d++) {
        float v = in[i * DIM + d] * g_scale[d];
        out[i * DIM + d] = v;
        s += v * v;
    }
    sq[i] = s;
}

__global__ void k_build_knn() {
    __shared__ float A[32][DIM];
    __shared__ float B[32][DIM + 1];
    int bi = blockIdx.y * 32, bj = blockIdx.x * 32;
    int t = threadIdx.x;
    for (int idx = t; idx < 32 * DIM; idx += 256) {
        int r = idx / DIM, d = idx % DIM;
        A[r][d] = g_xs[(bi + r) * DIM + d];
        B[r][d] = g_xs[(bj + r) * DIM + d];
    }
    __syncthreads();
    float sf2 = g_params[0], sn2 = g_params[1];
    int tx = t & 31, ty = t >> 5;
    int j = bj + tx;
    float sqj = g_sqx[j];
#pragma unroll
    for (int q = 0; q < 4; q++) {
        int li = ty * 4 + q, i = bi + li;
        float dot = 0.f;
#pragma unroll
        for (int d = 0; d < DIM; d++) dot += A[li][d] * B[tx][d];
        float d2 = fmaxf(g_sqx[i] + sqj - 2.f * dot, 0.f);
        float v = sf2 * expf(-d2);
        if (i == j) v += sn2;
        g_K  [(size_t)i * NTR + j] = v;
        g_Ktf[(size_t)i * NTR + j] = tf32r(v);
    }
}

__global__ void k_build_ks() {
    __shared__ float A[32][DIM];
    __shared__ float B[32][DIM + 1];
    int bi = blockIdx.y * 32, bj = blockIdx.x * 32;
    int t = threadIdx.x;
    for (int idx = t; idx < 32 * DIM; idx += 256) {
        int r = idx / DIM, d = idx % DIM;
        A[r][d] = g_xs[(bi + r) * DIM + d];
        B[r][d] = g_ts[(bj + r) * DIM + d];
    }
    __syncthreads();
    float sf2 = g_params[0];
    int tx = t & 31, ty = t >> 5;
    int j = bj + tx;
    float sqj = g_sqt[j];
#pragma unroll
    for (int q = 0; q < 4; q++) {
        int li = ty * 4 + q, i = bi + li;
        float dot = 0.f;
#pragma unroll
        for (int d = 0; d < DIM; d++) dot += A[li][d] * B[tx][d];
        float d2 = fmaxf(g_sqx[i] + sqj - 2.f * dot, 0.f);
        float v = sf2 * expf(-d2);
        g_Ks  [(size_t)i * NTE + j] = v;
        g_Kstf[(size_t)i * NTE + j] = tf32r(v);
    }
}

// ---- row sums (deterministic, warp per row) ----
__global__ void k_rowsum() {
    int t = threadIdx.x, lane = t & 31, w = t >> 5;
    int row = blockIdx.x * 8 + w;
    const float* Kr = g_K + (size_t)row * NTR;
    float s = 0.f;
    for (int j = lane; j < NTR; j += 32) s += Kr[j];
#pragma unroll
    for (int o = 16; o; o >>= 1) s += __shfl_down_sync(0xffffffffu, s, o);
    if (lane == 0) g_rowsum[row] = s;
}

// ---- spectrum bounds -> deg-4 poly coeffs + cheb schedule ----
__global__ void k_spec() {
    __shared__ float sm[1024];
    int t = threadIdx.x;
    float m = 0.f;
    for (int i = t; i < NTR; i += 1024) m = fmaxf(m, g_rowsum[i]);
    sm[t] = m;
    __syncthreads();
    for (int o = 512; o; o >>= 1) {
        if (t < o) sm[t] = fmaxf(sm[t], sm[t + o]);
        __syncthreads();
    }
    if (t == 0) {
        float b = sm[0];
        float sf2 = g_params[0], sn2 = g_params[1];
        float diag = sf2 + sn2;
        float a = fmaxf(sn2, 2.f * diag - b);
        if (!(a < b)) a = 0.5f * b;
        float theta = 0.5f * (a + b);
        float delta = fmaxf(0.5f * (b - a), 1e-6f * theta);
        float gamma = theta / delta;
        float rho   = 1.f / (gamma + sqrtf(gamma * gamma - 1.f));
        float r2 = rho * rho, r3 = r2 * rho, r4 = r2 * r2;
        float s = 2.f * rho / (delta * (1.f - r2));
        g_poly[0] = s * (1.f - 2.f * r2 + 2.f * r4);
        g_poly[1] = s * (-2.f * rho + 6.f * r3);
        g_poly[2] = s * (4.f * r2 - 16.f * r4);
        g_poly[3] = s * (-8.f * r3);
        g_poly[4] = s * (16.f * r4);
        g_spec[0] = theta; g_spec[1] = delta; g_spec[2] = 1.f / theta;
        float sig1 = gamma, rc = 1.f / sig1;
        for (int k = 1; k <= NIT + 1; k++) {
            float rn = 1.f / (2.f * sig1 - rc);
            g_c1[k] = rn * rc;
            g_c2[k] = 2.f * rn / delta;
            rc = rn;
        }
    }
}

// ---- big tensor GEMM: Z = tf32r((A*B - theta*B) / delta), NN, K-dim=4096 ----
// Round-9 proven config: 128 threads, 128x128 tile, warp grid 2x2, 2 blocks/SM
__global__ void __launch_bounds__(128, 2) k_gemmU(
    const float* __restrict__ A,     // g_Ktf, lda = NTR
    const float* __restrict__ B,     // rounded input, ldb = NTE
    float* __restrict__ Z)           // ldc = NTE
{
    extern __shared__ float sm[];
    constexpr int ASTG = 128 * 20;
    constexpr int BSTG = 16 * 136;
    constexpr int NS   = NTR / 16;   // 256 slices
    const int row0 = blockIdx.y * 128, col0 = blockIdx.x * 128;
    const int t = threadIdx.x;
    const int lane = t & 31, wid = t >> 5;
    const int wm = wid & 1, wn = wid >> 1;     // 2 x 2 warp grid
    const int g = lane >> 2, tig = lane & 3;
    const uint32_t smbase = (uint32_t)__cvta_generic_to_shared(sm);
    const int bkk = t >> 3, bcq = t & 7;       // B staging: 16 rows x 8 col-chunks

    const float theta = g_spec[0];
    const float idel  = 1.f / g_spec[1];

    auto issue = [&](int s, int stg) {
        const int k0 = s * 16;
        const float* srcA = A + (size_t)(row0 + t) * NTR + k0;
        uint32_t dstA = smbase + (uint32_t)(stg * ASTG + t * 20) * 4u;
#pragma unroll
        for (int j = 0; j < 4; j++) cpa16(dstA + j * 16, srcA + j * 4);
        const float* srcB = B + (size_t)(k0 + bkk) * NTE + col0 + bcq * 4;
        uint32_t dstB = smbase + (uint32_t)(3 * ASTG + stg * BSTG + bkk * 136 + bcq * 4) * 4u;
#pragma unroll
        for (int j = 0; j < 4; j++) cpa16(dstB + j * 128, srcB + j * 32);
        asm volatile("cp.async.commit_group;\n");
    };

    float acc[4][8][4];
#pragma unroll
    for (int i = 0; i < 4; i++)
#pragma unroll
        for (int j = 0; j < 8; j++)
#pragma unroll
            for (int q = 0; q < 4; q++) acc[i][j][q] = 0.f;

    issue(0, 0); issue(1, 1);
    int cur = 0, nxt = 2;
    for (int s = 0; s < NS; s++) {
        if (s < NS - 1) asm volatile("cp.async.wait_group 1;\n");
        else            asm volatile("cp.async.wait_group 0;\n");
        __syncthreads();
        if (s + 2 < NS) issue(s + 2, nxt);
        const float* Asb = sm + cur * ASTG;
        const float* Bsb = sm + 3 * ASTG + cur * BSTG;
#pragma unroll
        for (int kf = 0; kf < 2; kf++) {
            const int kb = kf * 8;
            uint32_t a[4][4], b[8][2];
#pragma unroll
            for (int mt = 0; mt < 4; mt++) {
                int rb = wm * 64 + mt * 16 + g;
                a[mt][0] = __float_as_uint(Asb[rb * 20 + kb + tig]);
                a[mt][1] = __float_as_uint(Asb[(rb + 8) * 20 + kb + tig]);
                a[mt][2] = __float_as_uint(Asb[rb * 20 + kb + tig + 4]);
                a[mt][3] = __float_as_uint(Asb[(rb + 8) * 20 + kb + tig + 4]);
            }
#pragma unroll
            for (int nt = 0; nt < 8; nt++) {
                int cb = wn * 64 + nt * 8 + g;
                b[nt][0] = __float_as_uint(Bsb[(kb + tig) * 136 + cb]);
                b[nt][1] = __float_as_uint(Bsb[(kb + tig + 4) * 136 + cb]);
            }
#pragma unroll
            for (int mt = 0; mt < 4; mt++)
#pragma unroll
                for (int nt = 0; nt < 8; nt++)
                    mma_tf32(acc[mt][nt], a[mt], b[nt]);
        }
        __syncthreads();
        cur = (cur == 2) ? 0 : cur + 1;
        nxt = (nxt == 2) ? 0 : nxt + 1;
    }

    // epilogue: Z = tf32r((acc - theta*B)/delta)
#pragma unroll
    for (int mt = 0; mt < 4; mt++) {
        int r0 = row0 + wm * 64 + mt * 16 + g;
#pragma unroll
        for (int nt = 0; nt < 8; nt++) {
            int c = col0 + wn * 64 + nt * 8 + tig * 2;
            float2 x0 = *(const float2*)(B + (size_t)r0 * NTE + c);
            float2 x1 = *(const float2*)(B + (size_t)(r0 + 8) * NTE + c);
            *(float2*)(Z + (size_t)r0 * NTE + c) = make_float2(
                tf32r((acc[mt][nt][0] - theta * x0.x) * idel),
                tf32r((acc[mt][nt][1] - theta * x0.y) * idel));
            *(float2*)(Z + (size_t)(r0 + 8) * NTE + c) = make_float2(
                tf32r((acc[mt][nt][2] - theta * x1.x) * idel),
                tf32r((acc[mt][nt][3] - theta * x1.y) * idel));
        }
    }
}

// ---- Chebyshev semi-iteration for alpha = K^{-1} y (round-9 launched form) ----
__global__ void k_cheb_init(const float* __restrict__ y) {
    int i = blockIdx.x * 256 + threadIdx.x;
    if (i >= NTR) return;
    g_xv[i] = 0.f;
    g_rv[i] = y[i];
    g_da[i] = y[i] * g_spec[2];
}

__global__ void k_cheb_iter(const float* __restrict__ din, float* __restrict__ dout, int k) {
    int t = threadIdx.x, lane = t & 31, w = t >> 5;
    int row = blockIdx.x * 8 + w;
    const float4* Kr = (const float4*)(g_K + (size_t)row * NTR);
    const float4* dv4 = (const float4*)din;
    float s = 0.f;
    for (int j = lane; j < NTR / 4; j += 32) {
        float4 kv = Kr[j], dd = dv4[j];
        s += kv.x * dd.x + kv.y * dd.y + kv.z * dd.z + kv.w * dd.w;
    }
#pragma unroll
    for (int o = 16; o; o >>= 1) s += __shfl_down_sync(0xffffffffu, s, o);
    if (lane == 0) {
        float dv = din[row];
        g_xv[row] += dv;
        float rv = g_rv[row] - s;
        g_rv[row] = rv;
        dout[row] = g_c1[k] * dv + g_c2[k] * rv;
    }
}

__global__ void k_axpy_final(const float* __restrict__ d) {
    int i = blockIdx.x * 256 + threadIdx.x;
    if (i < NTR) g_xv[i] += d[i];
}

// ---- fused dots: mean partial + 5 moment partials (round-9 form) ----
__global__ void k_dots() {            // grid (NTE/128, 8), 128 threads
    __shared__ float sa[512];
    int t = threadIdx.x;
    int n0 = blockIdx.y * 512;
    for (int q = t; q < 512; q += 128) sa[q] = g_xv[n0 + q];
    __syncthreads();
    int m = blockIdx.x * 128 + t;
    float dm = 0, d00 = 0, d01 = 0, d11 = 0, d12 = 0, d22 = 0;
    for (int q = 0; q < 512; q++) {
        size_t off = (size_t)(n0 + q) * NTE + m;
        float kf = g_Ks[off];
        float z1 = g_Z1[off], z2 = g_Z2[off];
        dm  += kf * sa[q];
        d00 += kf * kf; d01 += kf * z1; d11 += z1 * z1;
        d12 += z1 * z2; d22 += z2 * z2;
    }
    g_partM[blockIdx.y * NTE + m] = dm;
    float* pd = g_partD + (size_t)blockIdx.y * 5 * NTE + m;
    pd[0 * NTE] = d00; pd[1 * NTE] = d01; pd[2 * NTE] = d11;
    pd[3 * NTE] = d12; pd[4 * NTE] = d22;
}

__global__ void k_finalize(float* out) {
    int m = blockIdx.x * 256 + threadIdx.x;
    if (m >= NTE) return;
    float sm = 0.f, D[5] = {0, 0, 0, 0, 0};
    for (int p = 0; p < 8; p++) {
        sm += g_partM[p * NTE + m];
        const float* pd = g_partD + (size_t)p * 5 * NTE + m;
#pragma unroll
        for (int j = 0; j < 5; j++) D[j] += pd[j * NTE];
    }
    float q = 0.f;
#pragma unroll
    for (int j = 0; j < 5; j++) q += g_poly[j] * D[j];
    out[m] = sm;
    out[NTE + m] = g_params[0] + g_params[1] - q;
}

// ---- launch ----
extern "C" void kernel_launch(void* const* d_in, const int* in_sizes, int n_in,
                              void* d_out, int out_size)
{
    const float* train_x = (const float*)d_in[0];
    const float* train_y = (const float*)d_in[1];
    const float* test_x  = (const float*)d_in[2];
    const float* lsf2    = (const float*)d_in[3];
    const float* ll2     = (const float*)d_in[4];
    const float* lsn2    = (const float*)d_in[5];
    float* out = (float*)d_out;

    float *pKtf, *pKstf, *pZ1, *pZ2, *pXs, *pTs, *pSqx, *pSqt, *pDa, *pDb;
    cudaGetSymbolAddress((void**)&pKtf,  g_Ktf);
    cudaGetSymbolAddress((void**)&pKstf, g_Kstf);
    cudaGetSymbolAddress((void**)&pZ1,   g_Z1);
    cudaGetSymbolAddress((void**)&pZ2,   g_Z2);
    cudaGetSymbolAddress((void**)&pXs,   g_xs);
    cudaGetSymbolAddress((void**)&pTs,   g_ts);
    cudaGetSymbolAddress((void**)&pSqx,  g_sqx);
    cudaGetSymbolAddress((void**)&pSqt,  g_sqt);
    cudaGetSymbolAddress((void**)&pDa,   g_da);
    cudaGetSymbolAddress((void**)&pDb,   g_db);

    const int smem_gemm = 3 * (128 * 20 + 16 * 136) * sizeof(float);  // 56832
    cudaFuncSetAttribute(k_gemmU, cudaFuncAttributeMaxDynamicSharedMemorySize, smem_gemm);

    // ---- prologue (stream 0 = capture stream) ----
    k_prep<<<1, 32>>>(lsf2, ll2, lsn2);
    k_scale<<<(NTR + 255) / 256, 256>>>(train_x, pXs, pSqx, NTR);
    k_scale<<<(NTE + 255) / 256, 256>>>(test_x,  pTs, pSqt, NTE);
    k_build_knn<<<dim3(NTR / 32, NTR / 32), 256>>>();
    k_build_ks <<<dim3(NTE / 32, NTR / 32), 256>>>();
    k_rowsum<<<NTR / 8, 256>>>();
    k_spec<<<1, 1024>>>();

    // ---- fork: cheb chain on side stream, GEMMs on main stream ----
    cudaStream_t s2;
    cudaStreamCreateWithFlags(&s2, cudaStreamNonBlocking);
    cudaEvent_t eFork, eJoin;
    cudaEventCreateWithFlags(&eFork, cudaEventDisableTiming);
    cudaEventCreateWithFlags(&eJoin, cudaEventDisableTiming);

    cudaEventRecord(eFork, 0);
    cudaStreamWaitEvent(s2, eFork, 0);

    // side stream: alpha = K^{-1} y (13 launched iterations, fp32)
    k_cheb_init<<<(NTR + 255) / 256, 256, 0, s2>>>(train_y);
    float* din = pDa;
    float* dou = pDb;
    for (int k = 1; k <= NIT; k++) {
        k_cheb_iter<<<NTR / 8, 256, 0, s2>>>(din, dou, k);
        float* tmp = din; din = dou; dou = tmp;
    }
    k_axpy_final<<<(NTR + 255) / 256, 256, 0, s2>>>(din);
    cudaEventRecord(eJoin, s2);

    // main stream: Z1 = U*Ks, Z2 = U*Z1
    dim3 ggrid(NTE / 128, NTR / 128);
    k_gemmU<<<ggrid, 128, smem_gemm>>>(pKtf, pKstf, pZ1);
    k_gemmU<<<ggrid, 128, smem_gemm>>>(pKtf, pZ1,   pZ2);

    // join
    cudaStreamWaitEvent(0, eJoin, 0);

    k_dots<<<dim3(NTE / 128, 8), 128>>>();
    k_finalize<<<(NTE + 255) / 256, 256>>>(out);

    cudaEventDestroy(eFork);
    cudaEventDestroy(eJoin);
    cudaStreamDestroy(s2);
}

// round 14
// speedup vs baseline: 1.6408x; 1.1831x over previous
#include <cuda_runtime.h>
#include <cuda_bf16.h>
#include <cstdint>

constexpr int NTR = 4096;
constexpr int NTE = 2048;
constexpr int DIM = 16;
constexpr int NIT = 13;          // Chebyshev iterations for alpha

// ---- device scratch ----
__device__ float g_K   [(size_t)NTR * NTR];   // fp32 K (matvec + rowsum)
__device__ float g_Ktf [(size_t)NTR * NTR];   // tf32-rounded K (GEMM1 A)
__device__ __nv_bfloat16 g_Kbf[(size_t)NTR * NTR];   // bf16 K (GEMM2 A)
__device__ float g_Ks  [(size_t)NTR * NTE];   // fp32 Kstar (dots)
__device__ float g_Kstf[(size_t)NTR * NTE];   // rounded Kstar (GEMM1 B)
__device__ float g_Z1  [(size_t)NTR * NTE];   // fp32 Z1 (dots + epilogue corr)
__device__ __nv_bfloat16 g_Z1t[(size_t)NTE * NTR];   // bf16 Z1 transposed (GEMM2 B)
__device__ float g_Z2  [(size_t)NTR * NTE];
__device__ float g_xs[NTR * DIM];
__device__ float g_ts[NTE * DIM];
__device__ float g_sqx[NTR];
__device__ float g_sqt[NTE];
__device__ float g_rowsum[NTR];
__device__ float g_xv[NTR];                   // cheb solution (alpha)
__device__ float g_rv[NTR];                   // cheb residual
__device__ float g_da[NTR], g_db[NTR];        // cheb direction (double buffer)
__device__ float g_spec[4];                   // theta, delta, 1/theta
__device__ float g_poly[5];                   // s*a0..s*a4 (degree 4)
__device__ float g_c1[NIT + 2], g_c2[NIT + 2];
__device__ float g_partM[8 * NTE];
__device__ float g_partD[8 * 5 * NTE];
__device__ float g_params[2];                 // sigmaf2, sigman2
__device__ float g_scale[DIM];

// ---- helpers ----
__device__ __forceinline__ float tf32r(float x) {
    uint32_t u; asm("cvt.rna.tf32.f32 %0, %1;" : "=r"(u) : "f"(x));
    return __uint_as_float(u);
}
__device__ __forceinline__ void mma_tf32(float* d, const uint32_t* a, const uint32_t* b) {
    asm volatile(
        "mma.sync.aligned.m16n8k8.row.col.f32.tf32.tf32.f32 "
        "{%0,%1,%2,%3},{%4,%5,%6,%7},{%8,%9},{%0,%1,%2,%3};"
        : "+f"(d[0]), "+f"(d[1]), "+f"(d[2]), "+f"(d[3])
        : "r"(a[0]), "r"(a[1]), "r"(a[2]), "r"(a[3]), "r"(b[0]), "r"(b[1]));
}
__device__ __forceinline__ void mma_bf16(float* d, const uint32_t* a, const uint32_t* b) {
    asm volatile(
        "mma.sync.aligned.m16n8k16.row.col.f32.bf16.bf16.f32 "
        "{%0,%1,%2,%3},{%4,%5,%6,%7},{%8,%9},{%0,%1,%2,%3};"
        : "+f"(d[0]), "+f"(d[1]), "+f"(d[2]), "+f"(d[3])
        : "r"(a[0]), "r"(a[1]), "r"(a[2]), "r"(a[3]), "r"(b[0]), "r"(b[1]));
}
__device__ __forceinline__ void cpa16(uint32_t dst, const void* src) {
    asm volatile("cp.async.cg.shared.global [%0], [%1], 16;\n" :: "r"(dst), "l"(src));
}

// ---- prep / builders ----
__global__ void k_prep(const float* lsf2, const float* ll2, const float* lsn2) {
    int t = threadIdx.x;
    if (t == 0) { g_params[0] = expf(lsf2[0]); g_params[1] = expf(lsn2[0]); }
    if (t < DIM) g_scale[t] = sqrtf(0.5f * expf(-ll2[t]));
}

__global__ void k_scale(const float* __restrict__ in, float* __restrict__ out,
                        float* __restrict__ sq, int n) {
    int i = blockIdx.x * blockDim.x + threadIdx.x;
    if (i >= n) return;
    float s = 0.f;
#pragma unroll
    for (int d = 0; d < DIM; d++) {
        float v = in[i * DIM + d] * g_scale[d];
        out[i * DIM + d] = v;
        s += v * v;
    }
    sq[i] = s;
}

__global__ void k_build_knn() {
    __shared__ float A[32][DIM];
    __shared__ float B[32][DIM + 1];
    int bi = blockIdx.y * 32, bj = blockIdx.x * 32;
    int t = threadIdx.x;
    for (int idx = t; idx < 32 * DIM; idx += 256) {
        int r = idx / DIM, d = idx % DIM;
        A[r][d] = g_xs[(bi + r) * DIM + d];
        B[r][d] = g_xs[(bj + r) * DIM + d];
    }
    __syncthreads();
    float sf2 = g_params[0], sn2 = g_params[1];
    int tx = t & 31, ty = t >> 5;
    int j = bj + tx;
    float sqj = g_sqx[j];
#pragma unroll
    for (int q = 0; q < 4; q++) {
        int li = ty * 4 + q, i = bi + li;
        float dot = 0.f;
#pragma unroll
        for (int d = 0; d < DIM; d++) dot += A[li][d] * B[tx][d];
        float d2 = fmaxf(g_sqx[i] + sqj - 2.f * dot, 0.f);
        float v = sf2 * expf(-d2);
        if (i == j) v += sn2;
        g_K  [(size_t)i * NTR + j] = v;
        g_Ktf[(size_t)i * NTR + j] = tf32r(v);
        g_Kbf[(size_t)i * NTR + j] = __float2bfloat16(v);
    }
}

__global__ void k_build_ks() {
    __shared__ float A[32][DIM];
    __shared__ float B[32][DIM + 1];
    int bi = blockIdx.y * 32, bj = blockIdx.x * 32;
    int t = threadIdx.x;
    for (int idx = t; idx < 32 * DIM; idx += 256) {
        int r = idx / DIM, d = idx % DIM;
        A[r][d] = g_xs[(bi + r) * DIM + d];
        B[r][d] = g_ts[(bj + r) * DIM + d];
    }
    __syncthreads();
    float sf2 = g_params[0];
    int tx = t & 31, ty = t >> 5;
    int j = bj + tx;
    float sqj = g_sqt[j];
#pragma unroll
    for (int q = 0; q < 4; q++) {
        int li = ty * 4 + q, i = bi + li;
        float dot = 0.f;
#pragma unroll
        for (int d = 0; d < DIM; d++) dot += A[li][d] * B[tx][d];
        float d2 = fmaxf(g_sqx[i] + sqj - 2.f * dot, 0.f);
        float v = sf2 * expf(-d2);
        g_Ks  [(size_t)i * NTE + j] = v;
        g_Kstf[(size_t)i * NTE + j] = tf32r(v);
    }
}

// ---- row sums (deterministic, warp per row) ----
__global__ void k_rowsum() {
    int t = threadIdx.x, lane = t & 31, w = t >> 5;
    int row = blockIdx.x * 8 + w;
    const float* Kr = g_K + (size_t)row * NTR;
    float s = 0.f;
    for (int j = lane; j < NTR; j += 32) s += Kr[j];
#pragma unroll
    for (int o = 16; o; o >>= 1) s += __shfl_down_sync(0xffffffffu, s, o);
    if (lane == 0) g_rowsum[row] = s;
}

// ---- spectrum bounds -> deg-4 poly coeffs + cheb schedule ----
__global__ void k_spec() {
    __shared__ float sm[1024];
    int t = threadIdx.x;
    float m = 0.f;
    for (int i = t; i < NTR; i += 1024) m = fmaxf(m, g_rowsum[i]);
    sm[t] = m;
    __syncthreads();
    for (int o = 512; o; o >>= 1) {
        if (t < o) sm[t] = fmaxf(sm[t], sm[t + o]);
        __syncthreads();
    }
    if (t == 0) {
        float b = sm[0];
        float sf2 = g_params[0], sn2 = g_params[1];
        float diag = sf2 + sn2;
        float a = fmaxf(sn2, 2.f * diag - b);
        if (!(a < b)) a = 0.5f * b;
        float theta = 0.5f * (a + b);
        float delta = fmaxf(0.5f * (b - a), 1e-6f * theta);
        float gamma = theta / delta;
        float rho   = 1.f / (gamma + sqrtf(gamma * gamma - 1.f));
        float r2 = rho * rho, r3 = r2 * rho, r4 = r2 * r2;
        float s = 2.f * rho / (delta * (1.f - r2));
        g_poly[0] = s * (1.f - 2.f * r2 + 2.f * r4);
        g_poly[1] = s * (-2.f * rho + 6.f * r3);
        g_poly[2] = s * (4.f * r2 - 16.f * r4);
        g_poly[3] = s * (-8.f * r3);
        g_poly[4] = s * (16.f * r4);
        g_spec[0] = theta; g_spec[1] = delta; g_spec[2] = 1.f / theta;
        float sig1 = gamma, rc = 1.f / sig1;
        for (int k = 1; k <= NIT + 1; k++) {
            float rn = 1.f / (2.f * sig1 - rc);
            g_c1[k] = rn * rc;
            g_c2[k] = 2.f * rn / delta;
            rc = rn;
        }
    }
}

// ---- GEMM1 (tf32): Z1 = tf32r((Ktf*Kstf - theta*Kstf)/delta); also Z1t bf16 ----
// Round-9 proven config: 128 threads, 128x128 tile, warp grid 2x2, 2 blocks/SM
__global__ void __launch_bounds__(128, 2) k_gemmU(
    const float* __restrict__ A,     // g_Ktf, lda = NTR
    const float* __restrict__ B,     // rounded input, ldb = NTE
    float* __restrict__ Z)           // ldc = NTE
{
    extern __shared__ float sm[];
    constexpr int ASTG = 128 * 20;
    constexpr int BSTG = 16 * 136;
    constexpr int NS   = NTR / 16;   // 256 slices
    const int row0 = blockIdx.y * 128, col0 = blockIdx.x * 128;
    const int t = threadIdx.x;
    const int lane = t & 31, wid = t >> 5;
    const int wm = wid & 1, wn = wid >> 1;     // 2 x 2 warp grid
    const int g = lane >> 2, tig = lane & 3;
    const uint32_t smbase = (uint32_t)__cvta_generic_to_shared(sm);
    const int bkk = t >> 3, bcq = t & 7;       // B staging: 16 rows x 8 col-chunks

    const float theta = g_spec[0];
    const float idel  = 1.f / g_spec[1];

    auto issue = [&](int s, int stg) {
        const int k0 = s * 16;
        const float* srcA = A + (size_t)(row0 + t) * NTR + k0;
        uint32_t dstA = smbase + (uint32_t)(stg * ASTG + t * 20) * 4u;
#pragma unroll
        for (int j = 0; j < 4; j++) cpa16(dstA + j * 16, srcA + j * 4);
        const float* srcB = B + (size_t)(k0 + bkk) * NTE + col0 + bcq * 4;
        uint32_t dstB = smbase + (uint32_t)(3 * ASTG + stg * BSTG + bkk * 136 + bcq * 4) * 4u;
#pragma unroll
        for (int j = 0; j < 4; j++) cpa16(dstB + j * 128, srcB + j * 32);
        asm volatile("cp.async.commit_group;\n");
    };

    float acc[4][8][4];
#pragma unroll
    for (int i = 0; i < 4; i++)
#pragma unroll
        for (int j = 0; j < 8; j++)
#pragma unroll
            for (int q = 0; q < 4; q++) acc[i][j][q] = 0.f;

    issue(0, 0); issue(1, 1);
    int cur = 0, nxt = 2;
    for (int s = 0; s < NS; s++) {
        if (s < NS - 1) asm volatile("cp.async.wait_group 1;\n");
        else            asm volatile("cp.async.wait_group 0;\n");
        __syncthreads();
        if (s + 2 < NS) issue(s + 2, nxt);
        const float* Asb = sm + cur * ASTG;
        const float* Bsb = sm + 3 * ASTG + cur * BSTG;
#pragma unroll
        for (int kf = 0; kf < 2; kf++) {
            const int kb = kf * 8;
            uint32_t a[4][4], b[8][2];
#pragma unroll
            for (int mt = 0; mt < 4; mt++) {
                int rb = wm * 64 + mt * 16 + g;
                a[mt][0] = __float_as_uint(Asb[rb * 20 + kb + tig]);
                a[mt][1] = __float_as_uint(Asb[(rb + 8) * 20 + kb + tig]);
                a[mt][2] = __float_as_uint(Asb[rb * 20 + kb + tig + 4]);
                a[mt][3] = __float_as_uint(Asb[(rb + 8) * 20 + kb + tig + 4]);
            }
#pragma unroll
            for (int nt = 0; nt < 8; nt++) {
                int cb = wn * 64 + nt * 8 + g;
                b[nt][0] = __float_as_uint(Bsb[(kb + tig) * 136 + cb]);
                b[nt][1] = __float_as_uint(Bsb[(kb + tig + 4) * 136 + cb]);
            }
#pragma unroll
            for (int mt = 0; mt < 4; mt++)
#pragma unroll
                for (int nt = 0; nt < 8; nt++)
                    mma_tf32(acc[mt][nt], a[mt], b[nt]);
        }
        __syncthreads();
        cur = (cur == 2) ? 0 : cur + 1;
        nxt = (nxt == 2) ? 0 : nxt + 1;
    }

    // epilogue: Z1 = tf32r((acc - theta*B)/delta); Z1t = bf16(same), transposed
#pragma unroll
    for (int mt = 0; mt < 4; mt++) {
        int r0 = row0 + wm * 64 + mt * 16 + g;
#pragma unroll
        for (int nt = 0; nt < 8; nt++) {
            int c = col0 + wn * 64 + nt * 8 + tig * 2;
            float2 x0 = *(const float2*)(B + (size_t)r0 * NTE + c);
            float2 x1 = *(const float2*)(B + (size_t)(r0 + 8) * NTE + c);
            float v00 = (acc[mt][nt][0] - theta * x0.x) * idel;
            float v01 = (acc[mt][nt][1] - theta * x0.y) * idel;
            float v10 = (acc[mt][nt][2] - theta * x1.x) * idel;
            float v11 = (acc[mt][nt][3] - theta * x1.y) * idel;
            *(float2*)(Z + (size_t)r0 * NTE + c)       = make_float2(tf32r(v00), tf32r(v01));
            *(float2*)(Z + (size_t)(r0 + 8) * NTE + c) = make_float2(tf32r(v10), tf32r(v11));
            g_Z1t[(size_t)c * NTR + r0]           = __float2bfloat16(v00);
            g_Z1t[(size_t)(c + 1) * NTR + r0]     = __float2bfloat16(v01);
            g_Z1t[(size_t)c * NTR + r0 + 8]       = __float2bfloat16(v10);
            g_Z1t[(size_t)(c + 1) * NTR + r0 + 8] = __float2bfloat16(v11);
        }
    }
}

// ---- GEMM2 (bf16, m16n8k16): Z2 = (Kbf*Z1t - theta*Z1)/delta ----
// 128 threads, 128x128 tile, warp grid 2x2, BK=16, 3-stage cp.async
__global__ void __launch_bounds__(128, 2) k_gemmV(
    const __nv_bfloat16* __restrict__ A,    // g_Kbf [NTR][NTR]
    const __nv_bfloat16* __restrict__ Bt,   // g_Z1t [NTE][NTR] (n-major)
    const float* __restrict__ Bf,           // g_Z1 fp32 [NTR][NTE]
    float* __restrict__ Z)                  // g_Z2 [NTR][NTE]
{
    extern __shared__ __align__(16) char smc[];
    __nv_bfloat16* smh = (__nv_bfloat16*)smc;
    constexpr int ASTG = 128 * 24;   // bf16 units, row pad 24 (48B stride, conflict-free)
    constexpr int BSTG = 128 * 24;
    constexpr int NS   = NTR / 16;   // 256 slices
    const int row0 = blockIdx.y * 128, col0 = blockIdx.x * 128;
    const int t = threadIdx.x;
    const int lane = t & 31, wid = t >> 5;
    const int wm = wid & 1, wn = wid >> 1;     // 2 x 2 warp grid
    const int g = lane >> 2, tig = lane & 3;
    const uint32_t smbase = (uint32_t)__cvta_generic_to_shared(smc);

    const float theta = g_spec[0];
    const float idel  = 1.f / g_spec[1];

    auto issue = [&](int s, int stg) {
        const int k0 = s * 16;
        const __nv_bfloat16* srcA = A + (size_t)(row0 + t) * NTR + k0;
        uint32_t dstA = smbase + (uint32_t)(stg * ASTG + t * 24) * 2u;
        cpa16(dstA, srcA); cpa16(dstA + 16, srcA + 8);
        const __nv_bfloat16* srcB = Bt + (size_t)(col0 + t) * NTR + k0;
        uint32_t dstB = smbase + (uint32_t)(3 * ASTG + stg * BSTG + t * 24) * 2u;
        cpa16(dstB, srcB); cpa16(dstB + 16, srcB + 8);
        asm volatile("cp.async.commit_group;\n");
    };

    float acc[4][8][4];
#pragma unroll
    for (int i = 0; i < 4; i++)
#pragma unroll
        for (int j = 0; j < 8; j++)
#pragma unroll
            for (int q = 0; q < 4; q++) acc[i][j][q] = 0.f;

    issue(0, 0); issue(1, 1);
    int cur = 0, nxt = 2;
    for (int s = 0; s < NS; s++) {
        if (s < NS - 1) asm volatile("cp.async.wait_group 1;\n");
        else            asm volatile("cp.async.wait_group 0;\n");
        __syncthreads();
        if (s + 2 < NS) issue(s + 2, nxt);
        const uint32_t* Asb = (const uint32_t*)(smh + cur * ASTG);       // pairs: 12/row
        const uint32_t* Bsb = (const uint32_t*)(smh + 3 * ASTG + cur * BSTG);
        uint32_t a[4][4], b[8][2];
#pragma unroll
        for (int mt = 0; mt < 4; mt++) {
            int rb = wm * 64 + mt * 16 + g;
            a[mt][0] = Asb[rb * 12 + tig];
            a[mt][1] = Asb[(rb + 8) * 12 + tig];
            a[mt][2] = Asb[rb * 12 + 4 + tig];
            a[mt][3] = Asb[(rb + 8) * 12 + 4 + tig];
        }
#pragma unroll
        for (int nt = 0; nt < 8; nt++) {
            int cb = wn * 64 + nt * 8 + g;
            b[nt][0] = Bsb[cb * 12 + tig];
            b[nt][1] = Bsb[cb * 12 + 4 + tig];
        }
#pragma unroll
        for (int mt = 0; mt < 4; mt++)
#pragma unroll
            for (int nt = 0; nt < 8; nt++)
                mma_bf16(acc[mt][nt], a[mt], b[nt]);
        __syncthreads();
        cur = (cur == 2) ? 0 : cur + 1;
        nxt = (nxt == 2) ? 0 : nxt + 1;
    }

    // epilogue: Z2 = (acc - theta*Z1_fp32)/delta  (plain fp32, no rounding)
#pragma unroll
    for (int mt = 0; mt < 4; mt++) {
        int r0 = row0 + wm * 64 + mt * 16 + g;
#pragma unroll
        for (int nt = 0; nt < 8; nt++) {
            int c = col0 + wn * 64 + nt * 8 + tig * 2;
            float2 x0 = *(const float2*)(Bf + (size_t)r0 * NTE + c);
            float2 x1 = *(const float2*)(Bf + (size_t)(r0 + 8) * NTE + c);
            *(float2*)(Z + (size_t)r0 * NTE + c) = make_float2(
                (acc[mt][nt][0] - theta * x0.x) * idel,
                (acc[mt][nt][1] - theta * x0.y) * idel);
            *(float2*)(Z + (size_t)(r0 + 8) * NTE + c) = make_float2(
                (acc[mt][nt][2] - theta * x1.x) * idel,
                (acc[mt][nt][3] - theta * x1.y) * idel);
        }
    }
}

// ---- Chebyshev semi-iteration for alpha = K^{-1} y ----
__global__ void k_cheb_init(const float* __restrict__ y) {
    int i = blockIdx.x * 256 + threadIdx.x;
    if (i >= NTR) return;
    g_xv[i] = 0.f;
    g_rv[i] = y[i];
    g_da[i] = y[i] * g_spec[2];
}

__global__ void k_cheb_iter(const float* __restrict__ din, float* __restrict__ dout, int k) {
    int t = threadIdx.x, lane = t & 31, w = t >> 5;
    int row = blockIdx.x * 8 + w;
    const float4* Kr = (const float4*)(g_K + (size_t)row * NTR);
    const float4* dv4 = (const float4*)din;
    float s = 0.f;
    for (int j = lane; j < NTR / 4; j += 32) {
        float4 kv = Kr[j], dd = dv4[j];
        s += kv.x * dd.x + kv.y * dd.y + kv.z * dd.z + kv.w * dd.w;
    }
#pragma unroll
    for (int o = 16; o; o >>= 1) s += __shfl_down_sync(0xffffffffu, s, o);
    if (lane == 0) {
        float dv = din[row];
        g_xv[row] += dv;
        float rv = g_rv[row] - s;
        g_rv[row] = rv;
        dout[row] = g_c1[k] * dv + g_c2[k] * rv;
    }
}

__global__ void k_axpy_final(const float* __restrict__ d) {
    int i = blockIdx.x * 256 + threadIdx.x;
    if (i < NTR) g_xv[i] += d[i];
}

// ---- fused dots: mean partial + 5 moment partials ----
__global__ void k_dots() {            // grid (NTE/128, 8), 128 threads
    __shared__ float sa[512];
    int t = threadIdx.x;
    int n0 = blockIdx.y * 512;
    for (int q = t; q < 512; q += 128) sa[q] = g_xv[n0 + q];
    __syncthreads();
    int m = blockIdx.x * 128 + t;
    float dm = 0, d00 = 0, d01 = 0, d11 = 0, d12 = 0, d22 = 0;
    for (int q = 0; q < 512; q++) {
        size_t off = (size_t)(n0 + q) * NTE + m;
        float kf = g_Ks[off];
        float z1 = g_Z1[off], z2 = g_Z2[off];
        dm  += kf * sa[q];
        d00 += kf * kf; d01 += kf * z1; d11 += z1 * z1;
        d12 += z1 * z2; d22 += z2 * z2;
    }
    g_partM[blockIdx.y * NTE + m] = dm;
    float* pd = g_partD + (size_t)blockIdx.y * 5 * NTE + m;
    pd[0 * NTE] = d00; pd[1 * NTE] = d01; pd[2 * NTE] = d11;
    pd[3 * NTE] = d12; pd[4 * NTE] = d22;
}

__global__ void k_finalize(float* out) {
    int m = blockIdx.x * 256 + threadIdx.x;
    if (m >= NTE) return;
    float sm = 0.f, D[5] = {0, 0, 0, 0, 0};
    for (int p = 0; p < 8; p++) {
        sm += g_partM[p * NTE + m];
        const float* pd = g_partD + (size_t)p * 5 * NTE + m;
#pragma unroll
        for (int j = 0; j < 5; j++) D[j] += pd[j * NTE];
    }
    float q = 0.f;
#pragma unroll
    for (int j = 0; j < 5; j++) q += g_poly[j] * D[j];
    out[m] = sm;
    out[NTE + m] = g_params[0] + g_params[1] - q;
}

// ---- launch ----
extern "C" void kernel_launch(void* const* d_in, const int* in_sizes, int n_in,
                              void* d_out, int out_size)
{
    const float* train_x = (const float*)d_in[0];
    const float* train_y = (const float*)d_in[1];
    const float* test_x  = (const float*)d_in[2];
    const float* lsf2    = (const float*)d_in[3];
    const float* ll2     = (const float*)d_in[4];
    const float* lsn2    = (const float*)d_in[5];
    float* out = (float*)d_out;

    float *pKtf, *pKstf, *pZ1, *pZ2, *pXs, *pTs, *pSqx, *pSqt, *pDa, *pDb;
    __nv_bfloat16 *pKbf, *pZ1t;
    cudaGetSymbolAddress((void**)&pKtf,  g_Ktf);
    cudaGetSymbolAddress((void**)&pKbf,  g_Kbf);
    cudaGetSymbolAddress((void**)&pKstf, g_Kstf);
    cudaGetSymbolAddress((void**)&pZ1,   g_Z1);
    cudaGetSymbolAddress((void**)&pZ1t,  g_Z1t);
    cudaGetSymbolAddress((void**)&pZ2,   g_Z2);
    cudaGetSymbolAddress((void**)&pXs,   g_xs);
    cudaGetSymbolAddress((void**)&pTs,   g_ts);
    cudaGetSymbolAddress((void**)&pSqx,  g_sqx);
    cudaGetSymbolAddress((void**)&pSqt,  g_sqt);
    cudaGetSymbolAddress((void**)&pDa,   g_da);
    cudaGetSymbolAddress((void**)&pDb,   g_db);

    const int smem_g1 = 3 * (128 * 20 + 16 * 136) * sizeof(float);            // 56832
    const int smem_g2 = 3 * (128 * 24 + 128 * 24) * 2;                        // 36864
    cudaFuncSetAttribute(k_gemmU, cudaFuncAttributeMaxDynamicSharedMemorySize, smem_g1);
    cudaFuncSetAttribute(k_gemmV, cudaFuncAttributeMaxDynamicSharedMemorySize, smem_g2);

    // ---- prologue ----
    k_prep<<<1, 32>>>(lsf2, ll2, lsn2);
    k_scale<<<(NTR + 255) / 256, 256>>>(train_x, pXs, pSqx, NTR);
    k_scale<<<(NTE + 255) / 256, 256>>>(test_x,  pTs, pSqt, NTE);
    k_build_knn<<<dim3(NTR / 32, NTR / 32), 256>>>();
    k_build_ks <<<dim3(NTE / 32, NTR / 32), 256>>>();
    k_rowsum<<<NTR / 8, 256>>>();
    k_spec<<<1, 1024>>>();

    // ---- fork: cheb chain on side stream, GEMMs on main stream ----
    cudaStream_t s2;
    cudaStreamCreateWithFlags(&s2, cudaStreamNonBlocking);
    cudaEvent_t eFork, eJoin;
    cudaEventCreateWithFlags(&eFork, cudaEventDisableTiming);
    cudaEventCreateWithFlags(&eJoin, cudaEventDisableTiming);

    cudaEventRecord(eFork, 0);
    cudaStreamWaitEvent(s2, eFork, 0);

    k_cheb_init<<<(NTR + 255) / 256, 256, 0, s2>>>(train_y);
    float* din = pDa;
    float* dou = pDb;
    for (int k = 1; k <= NIT; k++) {
        k_cheb_iter<<<NTR / 8, 256, 0, s2>>>(din, dou, k);
        float* tmp = din; din = dou; dou = tmp;
    }
    k_axpy_final<<<(NTR + 255) / 256, 256, 0, s2>>>(din);
    cudaEventRecord(eJoin, s2);

    // main stream: Z1 (tf32) then Z2 (bf16)
    dim3 ggrid(NTE / 128, NTR / 128);
    k_gemmU<<<ggrid, 128, smem_g1>>>(pKtf, pKstf, pZ1);
    k_gemmV<<<ggrid, 128, smem_g2>>>(pKbf, pZ1t, pZ1, pZ2);

    cudaStreamWaitEvent(0, eJoin, 0);

    k_dots<<<dim3(NTE / 128, 8), 128>>>();
    k_finalize<<<(NTE + 255) / 256, 256>>>(out);

    cudaEventDestroy(eFork);
    cudaEventDestroy(eJoin);
    cudaStreamDestroy(s2);
}

// round 15
// speedup vs baseline: 1.9565x; 1.1924x over previous
#include <cuda_runtime.h>
#include <cuda_bf16.h>
#include <cstdint>

constexpr int NTR = 4096;
constexpr int NTE = 2048;
constexpr int DIM = 16;
constexpr int NIT = 13;          // Chebyshev iterations for alpha

// ---- device scratch ----
__device__ float g_K   [(size_t)NTR * NTR];   // fp32 K (matvec + rowsum)
__device__ __nv_bfloat16 g_Kbf [(size_t)NTR * NTR];  // bf16 K (GEMM A)
__device__ float g_Ks  [(size_t)NTR * NTE];   // fp32 Kstar (dots + GEMM1 corr)
__device__ __nv_bfloat16 g_Kst [(size_t)NTE * NTR];  // bf16 Ks^T (GEMM1 B)
__device__ float g_Z1  [(size_t)NTR * NTE];   // fp32 Z1 (dots + GEMM2 corr)
__device__ __nv_bfloat16 g_Z1t [(size_t)NTE * NTR];  // bf16 Z1^T (GEMM2 B)
__device__ float g_Z2  [(size_t)NTR * NTE];
__device__ float g_xs[NTR * DIM];
__device__ float g_ts[NTE * DIM];
__device__ float g_sqx[NTR];
__device__ float g_sqt[NTE];
__device__ float g_rowsum[NTR];
__device__ float g_xv[NTR];                   // cheb solution (alpha)
__device__ float g_rv[NTR];                   // cheb residual
__device__ float g_da[NTR], g_db[NTR];        // cheb direction (double buffer)
__device__ float g_spec[4];                   // theta, delta, 1/theta
__device__ float g_poly[5];                   // s*a0..s*a4 (degree 4)
__device__ float g_c1[NIT + 2], g_c2[NIT + 2];
__device__ float g_partM[8 * NTE];
__device__ float g_partD[8 * 5 * NTE];
__device__ float g_params[2];                 // sigmaf2, sigman2
__device__ float g_scale[DIM];

// ---- helpers ----
__device__ __forceinline__ void mma_bf16(float* d, const uint32_t* a, const uint32_t* b) {
    asm volatile(
        "mma.sync.aligned.m16n8k16.row.col.f32.bf16.bf16.f32 "
        "{%0,%1,%2,%3},{%4,%5,%6,%7},{%8,%9},{%0,%1,%2,%3};"
        : "+f"(d[0]), "+f"(d[1]), "+f"(d[2]), "+f"(d[3])
        : "r"(a[0]), "r"(a[1]), "r"(a[2]), "r"(a[3]), "r"(b[0]), "r"(b[1]));
}
__device__ __forceinline__ void cpa16(uint32_t dst, const void* src) {
    asm volatile("cp.async.cg.shared.global [%0], [%1], 16;\n" :: "r"(dst), "l"(src));
}

// ---- prep / builders ----
__global__ void k_prep(const float* lsf2, const float* ll2, const float* lsn2) {
    int t = threadIdx.x;
    if (t == 0) { g_params[0] = expf(lsf2[0]); g_params[1] = expf(lsn2[0]); }
    if (t < DIM) g_scale[t] = sqrtf(0.5f * expf(-ll2[t]));
}

__global__ void k_scale(const float* __restrict__ in, float* __restrict__ out,
                        float* __restrict__ sq, int n) {
    int i = blockIdx.x * blockDim.x + threadIdx.x;
    if (i >= n) return;
    float s = 0.f;
#pragma unroll
    for (int d = 0; d < DIM; d++) {
        float v = in[i * DIM + d] * g_scale[d];
        out[i * DIM + d] = v;
        s += v * v;
    }
    sq[i] = s;
}

__global__ void k_build_knn() {
    __shared__ float A[32][DIM];
    __shared__ float B[32][DIM + 1];
    int bi = blockIdx.y * 32, bj = blockIdx.x * 32;
    int t = threadIdx.x;
    for (int idx = t; idx < 32 * DIM; idx += 256) {
        int r = idx / DIM, d = idx % DIM;
        A[r][d] = g_xs[(bi + r) * DIM + d];
        B[r][d] = g_xs[(bj + r) * DIM + d];
    }
    __syncthreads();
    float sf2 = g_params[0], sn2 = g_params[1];
    int tx = t & 31, ty = t >> 5;
    int j = bj + tx;
    float sqj = g_sqx[j];
#pragma unroll
    for (int q = 0; q < 4; q++) {
        int li = ty * 4 + q, i = bi + li;
        float dot = 0.f;
#pragma unroll
        for (int d = 0; d < DIM; d++) dot += A[li][d] * B[tx][d];
        float d2 = fmaxf(g_sqx[i] + sqj - 2.f * dot, 0.f);
        float v = sf2 * expf(-d2);
        if (i == j) v += sn2;
        g_K  [(size_t)i * NTR + j] = v;
        g_Kbf[(size_t)i * NTR + j] = __float2bfloat16(v);
    }
}

__global__ void k_build_ks() {
    __shared__ float A[32][DIM];
    __shared__ float B[32][DIM + 1];
    int bi = blockIdx.y * 32, bj = blockIdx.x * 32;
    int t = threadIdx.x;
    for (int idx = t; idx < 32 * DIM; idx += 256) {
        int r = idx / DIM, d = idx % DIM;
        A[r][d] = g_xs[(bi + r) * DIM + d];
        B[r][d] = g_ts[(bj + r) * DIM + d];
    }
    __syncthreads();
    float sf2 = g_params[0];
    int tx = t & 31, ty = t >> 5;
    int j = bj + tx;
    float sqj = g_sqt[j];
#pragma unroll
    for (int q = 0; q < 4; q++) {
        int li = ty * 4 + q, i = bi + li;
        float dot = 0.f;
#pragma unroll
        for (int d = 0; d < DIM; d++) dot += A[li][d] * B[tx][d];
        float d2 = fmaxf(g_sqx[i] + sqj - 2.f * dot, 0.f);
        float v = sf2 * expf(-d2);
        g_Ks [(size_t)i * NTE + j] = v;
        g_Kst[(size_t)j * NTR + i] = __float2bfloat16(v);   // transposed bf16
    }
}

// ---- row sums (deterministic, warp per row) ----
__global__ void k_rowsum() {
    int t = threadIdx.x, lane = t & 31, w = t >> 5;
    int row = blockIdx.x * 8 + w;
    const float* Kr = g_K + (size_t)row * NTR;
    float s = 0.f;
    for (int j = lane; j < NTR; j += 32) s += Kr[j];
#pragma unroll
    for (int o = 16; o; o >>= 1) s += __shfl_down_sync(0xffffffffu, s, o);
    if (lane == 0) g_rowsum[row] = s;
}

// ---- spectrum bounds -> deg-4 poly coeffs + cheb schedule ----
__global__ void k_spec() {
    __shared__ float sm[1024];
    int t = threadIdx.x;
    float m = 0.f;
    for (int i = t; i < NTR; i += 1024) m = fmaxf(m, g_rowsum[i]);
    sm[t] = m;
    __syncthreads();
    for (int o = 512; o; o >>= 1) {
        if (t < o) sm[t] = fmaxf(sm[t], sm[t + o]);
        __syncthreads();
    }
    if (t == 0) {
        float b = sm[0];
        float sf2 = g_params[0], sn2 = g_params[1];
        float diag = sf2 + sn2;
        float a = fmaxf(sn2, 2.f * diag - b);
        if (!(a < b)) a = 0.5f * b;
        float theta = 0.5f * (a + b);
        float delta = fmaxf(0.5f * (b - a), 1e-6f * theta);
        float gamma = theta / delta;
        float rho   = 1.f / (gamma + sqrtf(gamma * gamma - 1.f));
        float r2 = rho * rho, r3 = r2 * rho, r4 = r2 * r2;
        float s = 2.f * rho / (delta * (1.f - r2));
        g_poly[0] = s * (1.f - 2.f * r2 + 2.f * r4);
        g_poly[1] = s * (-2.f * rho + 6.f * r3);
        g_poly[2] = s * (4.f * r2 - 16.f * r4);
        g_poly[3] = s * (-8.f * r3);
        g_poly[4] = s * (16.f * r4);
        g_spec[0] = theta; g_spec[1] = delta; g_spec[2] = 1.f / theta;
        float sig1 = gamma, rc = 1.f / sig1;
        for (int k = 1; k <= NIT + 1; k++) {
            float rn = 1.f / (2.f * sig1 - rc);
            g_c1[k] = rn * rc;
            g_c2[k] = 2.f * rn / delta;
            rc = rn;
        }
    }
}

// ---- bf16 GEMM (m16n8k16): Z = (A*Bt^T - theta*Bf)/delta; optional Zt bf16 ----
// 128 threads, 128x128 tile, warp grid 2x2, BK=16, 3-stage cp.async
template <int WRITE_T>
__global__ void __launch_bounds__(128, 2) k_gemmB(
    const __nv_bfloat16* __restrict__ A,    // [NTR][NTR] bf16
    const __nv_bfloat16* __restrict__ Bt,   // [NTE][NTR] bf16 (n-major)
    const float* __restrict__ Bf,           // fp32 [NTR][NTE] (theta correction)
    float* __restrict__ Z)                  // fp32 [NTR][NTE]
{
    extern __shared__ __align__(16) char smc[];
    __nv_bfloat16* smh = (__nv_bfloat16*)smc;
    constexpr int ASTG = 128 * 24;   // bf16 units, row pad 24
    constexpr int BSTG = 128 * 24;
    constexpr int NS   = NTR / 16;   // 256 slices
    const int row0 = blockIdx.y * 128, col0 = blockIdx.x * 128;
    const int t = threadIdx.x;
    const int lane = t & 31, wid = t >> 5;
    const int wm = wid & 1, wn = wid >> 1;     // 2 x 2 warp grid
    const int g = lane >> 2, tig = lane & 3;
    const uint32_t smbase = (uint32_t)__cvta_generic_to_shared(smc);

    const float theta = g_spec[0];
    const float idel  = 1.f / g_spec[1];

    auto issue = [&](int s, int stg) {
        const int k0 = s * 16;
        const __nv_bfloat16* srcA = A + (size_t)(row0 + t) * NTR + k0;
        uint32_t dstA = smbase + (uint32_t)(stg * ASTG + t * 24) * 2u;
        cpa16(dstA, srcA); cpa16(dstA + 16, srcA + 8);
        const __nv_bfloat16* srcB = Bt + (size_t)(col0 + t) * NTR + k0;
        uint32_t dstB = smbase + (uint32_t)(3 * ASTG + stg * BSTG + t * 24) * 2u;
        cpa16(dstB, srcB); cpa16(dstB + 16, srcB + 8);
        asm volatile("cp.async.commit_group;\n");
    };

    float acc[4][8][4];
#pragma unroll
    for (int i = 0; i < 4; i++)
#pragma unroll
        for (int j = 0; j < 8; j++)
#pragma unroll
            for (int q = 0; q < 4; q++) acc[i][j][q] = 0.f;

    issue(0, 0); issue(1, 1);
    int cur = 0, nxt = 2;
    for (int s = 0; s < NS; s++) {
        if (s < NS - 1) asm volatile("cp.async.wait_group 1;\n");
        else            asm volatile("cp.async.wait_group 0;\n");
        __syncthreads();
        if (s + 2 < NS) issue(s + 2, nxt);
        const uint32_t* Asb = (const uint32_t*)(smh + cur * ASTG);       // 12 u32/row
        const uint32_t* Bsb = (const uint32_t*)(smh + 3 * ASTG + cur * BSTG);
        uint32_t a[4][4], b[8][2];
#pragma unroll
        for (int mt = 0; mt < 4; mt++) {
            int rb = wm * 64 + mt * 16 + g;
            a[mt][0] = Asb[rb * 12 + tig];
            a[mt][1] = Asb[(rb + 8) * 12 + tig];
            a[mt][2] = Asb[rb * 12 + 4 + tig];
            a[mt][3] = Asb[(rb + 8) * 12 + 4 + tig];
        }
#pragma unroll
        for (int nt = 0; nt < 8; nt++) {
            int cb = wn * 64 + nt * 8 + g;
            b[nt][0] = Bsb[cb * 12 + tig];
            b[nt][1] = Bsb[cb * 12 + 4 + tig];
        }
#pragma unroll
        for (int mt = 0; mt < 4; mt++)
#pragma unroll
            for (int nt = 0; nt < 8; nt++)
                mma_bf16(acc[mt][nt], a[mt], b[nt]);
        __syncthreads();
        cur = (cur == 2) ? 0 : cur + 1;
        nxt = (nxt == 2) ? 0 : nxt + 1;
    }

    // epilogue: Z = (acc - theta*Bf)/delta (fp32); optional transposed bf16 copy
#pragma unroll
    for (int mt = 0; mt < 4; mt++) {
        int r0 = row0 + wm * 64 + mt * 16 + g;
#pragma unroll
        for (int nt = 0; nt < 8; nt++) {
            int c = col0 + wn * 64 + nt * 8 + tig * 2;
            float2 x0 = *(const float2*)(Bf + (size_t)r0 * NTE + c);
            float2 x1 = *(const float2*)(Bf + (size_t)(r0 + 8) * NTE + c);
            float v00 = (acc[mt][nt][0] - theta * x0.x) * idel;
            float v01 = (acc[mt][nt][1] - theta * x0.y) * idel;
            float v10 = (acc[mt][nt][2] - theta * x1.x) * idel;
            float v11 = (acc[mt][nt][3] - theta * x1.y) * idel;
            *(float2*)(Z + (size_t)r0 * NTE + c)       = make_float2(v00, v01);
            *(float2*)(Z + (size_t)(r0 + 8) * NTE + c) = make_float2(v10, v11);
            if (WRITE_T) {
                g_Z1t[(size_t)c * NTR + r0]           = __float2bfloat16(v00);
                g_Z1t[(size_t)(c + 1) * NTR + r0]     = __float2bfloat16(v01);
                g_Z1t[(size_t)c * NTR + r0 + 8]       = __float2bfloat16(v10);
                g_Z1t[(size_t)(c + 1) * NTR + r0 + 8] = __float2bfloat16(v11);
            }
        }
    }
}

// ---- Chebyshev semi-iteration for alpha = K^{-1} y ----
__global__ void k_cheb_init(const float* __restrict__ y) {
    int i = blockIdx.x * 256 + threadIdx.x;
    if (i >= NTR) return;
    g_xv[i] = 0.f;
    g_rv[i] = y[i];
    g_da[i] = y[i] * g_spec[2];
}

__global__ void k_cheb_iter(const float* __restrict__ din, float* __restrict__ dout, int k) {
    int t = threadIdx.x, lane = t & 31, w = t >> 5;
    int row = blockIdx.x * 8 + w;
    const float4* Kr = (const float4*)(g_K + (size_t)row * NTR);
    const float4* dv4 = (const float4*)din;
    float s = 0.f;
    for (int j = lane; j < NTR / 4; j += 32) {
        float4 kv = Kr[j], dd = dv4[j];
        s += kv.x * dd.x + kv.y * dd.y + kv.z * dd.z + kv.w * dd.w;
    }
#pragma unroll
    for (int o = 16; o; o >>= 1) s += __shfl_down_sync(0xffffffffu, s, o);
    if (lane == 0) {
        float dv = din[row];
        g_xv[row] += dv;
        float rv = g_rv[row] - s;
        g_rv[row] = rv;
        dout[row] = g_c1[k] * dv + g_c2[k] * rv;
    }
}

__global__ void k_axpy_final(const float* __restrict__ d) {
    int i = blockIdx.x * 256 + threadIdx.x;
    if (i < NTR) g_xv[i] += d[i];
}

// ---- fused dots: mean partial + 5 moment partials ----
__global__ void k_dots() {            // grid (NTE/128, 8), 128 threads
    __shared__ float sa[512];
    int t = threadIdx.x;
    int n0 = blockIdx.y * 512;
    for (int q = t; q < 512; q += 128) sa[q] = g_xv[n0 + q];
    __syncthreads();
    int m = blockIdx.x * 128 + t;
    float dm = 0, d00 = 0, d01 = 0, d11 = 0, d12 = 0, d22 = 0;
    for (int q = 0; q < 512; q++) {
        size_t off = (size_t)(n0 + q) * NTE + m;
        float kf = g_Ks[off];
        float z1 = g_Z1[off], z2 = g_Z2[off];
        dm  += kf * sa[q];
        d00 += kf * kf; d01 += kf * z1; d11 += z1 * z1;
        d12 += z1 * z2; d22 += z2 * z2;
    }
    g_partM[blockIdx.y * NTE + m] = dm;
    float* pd = g_partD + (size_t)blockIdx.y * 5 * NTE + m;
    pd[0 * NTE] = d00; pd[1 * NTE] = d01; pd[2 * NTE] = d11;
    pd[3 * NTE] = d12; pd[4 * NTE] = d22;
}

__global__ void k_finalize(float* out) {
    int m = blockIdx.x * 256 + threadIdx.x;
    if (m >= NTE) return;
    float sm = 0.f, D[5] = {0, 0, 0, 0, 0};
    for (int p = 0; p < 8; p++) {
        sm += g_partM[p * NTE + m];
        const float* pd = g_partD + (size_t)p * 5 * NTE + m;
#pragma unroll
        for (int j = 0; j < 5; j++) D[j] += pd[j * NTE];
    }
    float q = 0.f;
#pragma unroll
    for (int j = 0; j < 5; j++) q += g_poly[j] * D[j];
    out[m] = sm;
    out[NTE + m] = g_params[0] + g_params[1] - q;
}

// ---- launch ----
extern "C" void kernel_launch(void* const* d_in, const int* in_sizes, int n_in,
                              void* d_out, int out_size)
{
    const float* train_x = (const float*)d_in[0];
    const float* train_y = (const float*)d_in[1];
    const float* test_x  = (const float*)d_in[2];
    const float* lsf2    = (const float*)d_in[3];
    const float* ll2     = (const float*)d_in[4];
    const float* lsn2    = (const float*)d_in[5];
    float* out = (float*)d_out;

    float *pKs, *pZ1, *pZ2, *pXs, *pTs, *pSqx, *pSqt, *pDa, *pDb;
    __nv_bfloat16 *pKbf, *pKst, *pZ1t;
    cudaGetSymbolAddress((void**)&pKbf, g_Kbf);
    cudaGetSymbolAddress((void**)&pKst, g_Kst);
    cudaGetSymbolAddress((void**)&pKs,  g_Ks);
    cudaGetSymbolAddress((void**)&pZ1,  g_Z1);
    cudaGetSymbolAddress((void**)&pZ1t, g_Z1t);
    cudaGetSymbolAddress((void**)&pZ2,  g_Z2);
    cudaGetSymbolAddress((void**)&pXs,  g_xs);
    cudaGetSymbolAddress((void**)&pTs,  g_ts);
    cudaGetSymbolAddress((void**)&pSqx, g_sqx);
    cudaGetSymbolAddress((void**)&pSqt, g_sqt);
    cudaGetSymbolAddress((void**)&pDa,  g_da);
    cudaGetSymbolAddress((void**)&pDb,  g_db);

    const int smem_g = 3 * (128 * 24 + 128 * 24) * 2;   // 36864
    cudaFuncSetAttribute(k_gemmB<1>, cudaFuncAttributeMaxDynamicSharedMemorySize, smem_g);
    cudaFuncSetAttribute(k_gemmB<0>, cudaFuncAttributeMaxDynamicSharedMemorySize, smem_g);

    // ---- prologue ----
    k_prep<<<1, 32>>>(lsf2, ll2, lsn2);
    k_scale<<<(NTR + 255) / 256, 256>>>(train_x, pXs, pSqx, NTR);
    k_scale<<<(NTE + 255) / 256, 256>>>(test_x,  pTs, pSqt, NTE);
    k_build_knn<<<dim3(NTR / 32, NTR / 32), 256>>>();
    k_build_ks <<<dim3(NTE / 32, NTR / 32), 256>>>();
    k_rowsum<<<NTR / 8, 256>>>();
    k_spec<<<1, 1024>>>();

    // ---- fork: cheb chain on side stream, GEMMs on main stream ----
    cudaStream_t s2;
    cudaStreamCreateWithFlags(&s2, cudaStreamNonBlocking);
    cudaEvent_t eFork, eJoin;
    cudaEventCreateWithFlags(&eFork, cudaEventDisableTiming);
    cudaEventCreateWithFlags(&eJoin, cudaEventDisableTiming);

    cudaEventRecord(eFork, 0);
    cudaStreamWaitEvent(s2, eFork, 0);

    k_cheb_init<<<(NTR + 255) / 256, 256, 0, s2>>>(train_y);
    float* din = pDa;
    float* dou = pDb;
    for (int k = 1; k <= NIT; k++) {
        k_cheb_iter<<<NTR / 8, 256, 0, s2>>>(din, dou, k);
        float* tmp = din; din = dou; dou = tmp;
    }
    k_axpy_final<<<(NTR + 255) / 256, 256, 0, s2>>>(din);
    cudaEventRecord(eJoin, s2);

    // main stream: Z1 then Z2 (both bf16 tensor GEMMs)
    dim3 ggrid(NTE / 128, NTR / 128);
    k_gemmB<1><<<ggrid, 128, smem_g>>>(pKbf, pKst, pKs, pZ1);
    k_gemmB<0><<<ggrid, 128, smem_g>>>(pKbf, pZ1t, pZ1, pZ2);

    cudaStreamWaitEvent(0, eJoin, 0);

    k_dots<<<dim3(NTE / 128, 8), 128>>>();
    k_finalize<<<(NTE + 255) / 256, 256>>>(out);

    cudaEventDestroy(eFork);
    cudaEventDestroy(eJoin);
    cudaStreamDestroy(s2);
}